// round 10
// baseline (speedup 1.0000x reference)
#include <cuda_runtime.h>
#include <cstddef>

// Problem constants
#define BB   2
#define SS   2048
#define DD   512
#define HH   8
#define DEP  64
#define BSD  (BB*SS*DD)

// ---------------- scratch (device globals; no allocation allowed) ----------------
__device__ float g_q[BB*HH*SS*DEP];   // [B,H,S,64] projected Q
__device__ float g_k[BB*HH*SS*DEP];   // [B,H,S,64] projected K
__device__ float g_v[BB*HH*SS*DEP];   // [B,H,S,64] projected V
__device__ float g_c[BB*SS*DD];       // [B,S,D] concat(attention)

// =================================================================================
// Projection GEMMs (unchanged from measured passing version)
// =================================================================================
__device__ __forceinline__ void gemm_body(const float* __restrict__ X,
                                          const float* __restrict__ W,
                                          const float* __restrict__ bias,
                                          float* __restrict__ out, int mode)
{
    __shared__ float Xs[16*132];
    __shared__ float Wt[16*132];
    const int t  = threadIdx.x;
    const int tx = t & 15, ty = t >> 4;
    const int m0 = blockIdx.x * 128, n0 = blockIdx.y * 128;

    float acc[8][8];
    #pragma unroll
    for (int i = 0; i < 8; i++)
        #pragma unroll
        for (int j = 0; j < 8; j++) acc[i][j] = 0.f;

    for (int kb = 0; kb < DD; kb += 16) {
        __syncthreads();
        #pragma unroll
        for (int i = 0; i < 8; i++) {
            int idx = t + i*256;
            int k = idx & 15, m = idx >> 4;
            Xs[k*132 + m] = X[(size_t)(m0 + m)*DD + kb + k];
        }
        #pragma unroll
        for (int i = 0; i < 8; i++) {
            int idx = t + i*256;
            int n = idx & 127, k = idx >> 7;
            Wt[k*132 + n] = W[(size_t)(kb + k)*DD + n0 + n];
        }
        __syncthreads();
        #pragma unroll
        for (int k = 0; k < 16; k++) {
            float4 a0 = *(const float4*)&Xs[k*132 + ty*8];
            float4 a1 = *(const float4*)&Xs[k*132 + ty*8 + 4];
            float4 b0 = *(const float4*)&Wt[k*132 + tx*8];
            float4 b1 = *(const float4*)&Wt[k*132 + tx*8 + 4];
            float a[8] = {a0.x,a0.y,a0.z,a0.w,a1.x,a1.y,a1.z,a1.w};
            float b[8] = {b0.x,b0.y,b0.z,b0.w,b1.x,b1.y,b1.z,b1.w};
            #pragma unroll
            for (int i = 0; i < 8; i++)
                #pragma unroll
                for (int j = 0; j < 8; j++) acc[i][j] += a[i]*b[j];
        }
    }

    #pragma unroll
    for (int i = 0; i < 8; i++) {
        int m = m0 + ty*8 + i;
        int b_ = m >> 11, s = m & (SS - 1);
        #pragma unroll
        for (int j = 0; j < 8; j++) {
            int n = n0 + tx*8 + j;
            float v = acc[i][j] + bias[n];
            if (mode == 0) {
                int h = n >> 6, d = n & 63;
                out[(((size_t)(b_*HH + h)*SS + s) << 6) + d] = v;
            } else {
                out[(size_t)m*DD + n] = v;
            }
        }
    }
}

__global__ __launch_bounds__(256, 2) void gemm_qkv(
    const float* __restrict__ q_in, const float* __restrict__ k_in,
    const float* __restrict__ v_in,
    const float* __restrict__ Wq, const float* __restrict__ bq,
    const float* __restrict__ Wk, const float* __restrict__ bk,
    const float* __restrict__ Wv, const float* __restrict__ bv,
    float* __restrict__ gq, float* __restrict__ gk, float* __restrict__ gv)
{
    const float *X, *W, *bias; float* out;
    if (blockIdx.z == 0)      { X = q_in; W = Wq; bias = bq; out = gq; }
    else if (blockIdx.z == 1) { X = k_in; W = Wk; bias = bk; out = gk; }
    else                      { X = v_in; W = Wv; bias = bv; out = gv; }
    gemm_body(X, W, bias, out, 0);
}

__global__ __launch_bounds__(256, 2) void gemm_out(
    const float* __restrict__ X, const float* __restrict__ W,
    const float* __restrict__ bias, float* __restrict__ out)
{
    gemm_body(X, W, bias, out, 1);
}

// =================================================================================
// Fused attention, 128-q tile per CTA, 256 threads, 1 CTA/SM.
//
// Phase 1 per 64-wide k-chunk: D(128x128) = Q(128x64) @ [K64 ; Enew64]^T with an
// 8x8 register tile; K-dots -> DK, E-dots -> 192-slot rolling ring RG[q][slot]
// (slot = (127 - qr + kl + 64*kt) mod 192; prologue fills slots [0,128)).
// Skew-gather l = (DK + RG)/8, causal mask, raw logits -> attn scratch,
// flash (max,sum) per row (2 threads/row).
// Phase 2: normalize weights (gmem round-trip), O(128x64) += W @ V with 8x4 tile.
//
// smem floats: Qs[64x132]@0, Bs[64x132]@8448, DK[128x68]@16896,
//   RG[128x196]@25600, rm@50688, rs@50816; total 50944 fl = 203776 B.
//   Phase 2 overlays: Vs[64x68]@8448, Wt[64x132]@16896.
// =================================================================================
#define P2Q 132
#define P2R 196
#define O2_BS 8448
#define O2_DK 16896
#define O2_RG 25600
#define O2_RM 50688
#define O2_RS 50816
#define SM2_BYTES (50944*4)

#define GEMM8X8(ACC) {                                                   \
    _Pragma("unroll")                                                    \
    for (int i = 0; i < 8; i++)                                          \
        _Pragma("unroll")                                                \
        for (int j = 0; j < 8; j++) ACC[i][j] = 0.f;                     \
    const float* qc = Qs + ty*8;                                         \
    const float* bc = Bs + tx*8;                                         \
    _Pragma("unroll 4")                                                  \
    for (int d = 0; d < 64; d++) {                                       \
        float4 a0 = *(const float4*)(qc + d*P2Q);                        \
        float4 a1 = *(const float4*)(qc + d*P2Q + 4);                    \
        float4 b0 = *(const float4*)(bc + d*P2Q);                        \
        float4 b1 = *(const float4*)(bc + d*P2Q + 4);                    \
        float a[8] = {a0.x,a0.y,a0.z,a0.w,a1.x,a1.y,a1.z,a1.w};          \
        float bb[8] = {b0.x,b0.y,b0.z,b0.w,b1.x,b1.y,b1.z,b1.w};         \
        _Pragma("unroll")                                                \
        for (int i = 0; i < 8; i++)                                      \
            _Pragma("unroll")                                            \
            for (int j = 0; j < 8; j++) ACC[i][j] += a[i]*bb[j];         \
    } }

__global__ __launch_bounds__(256, 1) void attn2(const float* __restrict__ E,
                                                float* __restrict__ attn)
{
    extern __shared__ float sm[];
    float* Qs = sm;              // [d][q] pitch 132
    float* Bs = sm + O2_BS;      // [d][col] pitch 132
    float* DK = sm + O2_DK;      // [q][k]  pitch 68
    float* RG = sm + O2_RG;      // [q][slot] pitch 196, 192 slots
    float* rm = sm + O2_RM;
    float* rs = sm + O2_RS;

    const int t  = threadIdx.x;
    const int qi = 15 - (int)blockIdx.x;     // big tiles first
    const int q0 = qi * 128;
    const int h  = blockIdx.y, b = blockIdx.z;
    const int bh = b*HH + h;
    const float* qb = g_q + (size_t)bh*SS*DEP;
    const float* kb = g_k + (size_t)bh*SS*DEP;
    const float* vb = g_v + (size_t)bh*SS*DEP;
    const int nch = 2*qi + 2;

    // Q tile 128x64 -> Qs[d][r]
    #pragma unroll
    for (int it = 0; it < 32; it++) {
        int idx = t + it*256;
        int r = idx >> 6, d = idx & 63;
        Qs[d*P2Q + r] = qb[(size_t)(q0 + r)*DEP + d];
    }
    // prologue E rows er0+[0,128)  (er0 = S-128-q0 >= 0, er < S)
    {
        const int er0 = SS - 128 - q0;
        #pragma unroll
        for (int it = 0; it < 32; it++) {
            int idx = t + it*256;
            int r = idx >> 6, d = idx & 63;
            Bs[d*P2Q + r] = E[(size_t)(er0 + r)*DEP + d];
        }
    }
    if (t < 128) { rm[t] = -1e30f; rs[t] = 0.f; }
    __syncthreads();

    const int tx = t & 15, ty = t >> 4;   // GEMM map: 8 q-rows x 8 cols
    const int qr = t >> 1, kh = t & 1;    // gather map: row qr, 32 k each

    // prologue GEMM -> ring slots [0,128)
    {
        float acc[8][8];
        GEMM8X8(acc)
        #pragma unroll
        for (int i = 0; i < 8; i++) {
            float* rr = RG + (ty*8 + i)*P2R + tx*8;
            ((float4*)rr)[0] = make_float4(acc[i][0], acc[i][1], acc[i][2], acc[i][3]);
            ((float4*)rr)[1] = make_float4(acc[i][4], acc[i][5], acc[i][6], acc[i][7]);
        }
    }
    __syncthreads();

    // ---------------- phase 1 ----------------
    for (int kt = 0; kt < nch; kt++) {
        const int k0 = kt*64;
        #pragma unroll
        for (int it = 0; it < 16; it++) {             // K -> cols [0,64)
            int idx = t + it*256;
            int i = idx >> 6, d = idx & 63;
            Bs[d*P2Q + i] = kb[(size_t)(k0 + i)*DEP + d];
        }
        {
            const int ern = SS - q0 + 64*kt;          // new E rows -> cols [64,128)
            #pragma unroll
            for (int it = 0; it < 16; it++) {
                int idx = t + it*256;
                int r = idx >> 6, d = idx & 63;
                int er = ern + r;
                Bs[d*P2Q + 64 + r] = (er < SS) ? E[(size_t)er*DEP + d] : 0.f;
            }
        }
        __syncthreads();

        float acc[8][8];
        GEMM8X8(acc)

        if (tx < 8) {                                  // K-dots -> DK[q][k]
            #pragma unroll
            for (int i = 0; i < 8; i++) {
                float* dr = DK + (ty*8 + i)*68 + tx*8;
                ((float4*)dr)[0] = make_float4(acc[i][0], acc[i][1], acc[i][2], acc[i][3]);
                ((float4*)dr)[1] = make_float4(acc[i][4], acc[i][5], acc[i][6], acc[i][7]);
            }
        } else {                                       // E-dots -> ring new slots
            const int sb = (128 + 64*kt) % 192;        // in {128,0,64}; sb+63 < 192
            const int c0 = sb + (tx - 8)*8;
            #pragma unroll
            for (int i = 0; i < 8; i++) {
                float* rr = RG + (ty*8 + i)*P2R + c0;
                ((float4*)rr)[0] = make_float4(acc[i][0], acc[i][1], acc[i][2], acc[i][3]);
                ((float4*)rr)[1] = make_float4(acc[i][4], acc[i][5], acc[i][6], acc[i][7]);
            }
        }
        __syncthreads();

        // gather + mask + stats + raw-logit store (32 per thread)
        {
            int bm = 127 - qr + (64*kt) % 192;         // < 256
            if (bm >= 192) bm -= 192;
            const float* dkr = DK + qr*68;
            const float* rgr = RG + qr*P2R;
            const int gq = q0 + qr;
            float l[32];
            float lmax = -1e30f;
            #pragma unroll
            for (int j = 0; j < 32; j++) {
                int kl = kh*32 + j;
                int slot = bm + kl; if (slot >= 192) slot -= 192;
                float v = dkr[kl] + rgr[slot];
                v = (k0 + kl <= gq) ? v*0.125f : -1e30f;
                l[j] = v;
                lmax = fmaxf(lmax, v);
            }
            float lsum = 0.f;
            #pragma unroll
            for (int j = 0; j < 32; j++) lsum += __expf(l[j] - lmax);

            float* ar = attn + ((size_t)bh*SS + gq)*SS + k0 + kh*32;
            #pragma unroll
            for (int j = 0; j < 32; j++) ar[j] = l[j];

            float om = __shfl_xor_sync(0xffffffffu, lmax, 1);
            float os = __shfl_xor_sync(0xffffffffu, lsum, 1);
            float nm = fmaxf(lmax, om);
            lsum = lsum*__expf(lmax - nm) + os*__expf(om - nm);
            lmax = nm;
            if (kh == 0) {
                float mo = rm[qr];
                float n2 = fmaxf(mo, lmax);
                rs[qr] = rs[qr]*__expf(mo - n2) + lsum*__expf(lmax - n2);
                rm[qr] = n2;
            }
        }
        __syncthreads();
    }

    const float rmax = rm[qr];
    const float rinv = 1.f / rs[qr];

    // ---------------- phase 2: normalize + O = W @ V ----------------
    float* Vs = sm + O2_BS;     // [k][d] pitch 68
    float* Wt = sm + O2_DK;     // [k][q] pitch 132 (8448 fits the 8704-float DK region)
    float Ov[8][4];
    #pragma unroll
    for (int i = 0; i < 8; i++)
        #pragma unroll
        for (int j = 0; j < 4; j++) Ov[i][j] = 0.f;

    for (int kt = 0; kt < nch; kt++) {
        const int k0 = kt*64;
        __syncthreads();        // previous-iteration Vs/Wt reads complete
        #pragma unroll
        for (int it = 0; it < 16; it++) {
            int idx = t + it*256;
            int i = idx >> 6, d = idx & 63;
            Vs[i*68 + d] = vb[(size_t)(k0 + i)*DEP + d];
        }
        float* ar = attn + ((size_t)bh*SS + q0 + qr)*SS + k0 + kh*32;
        #pragma unroll
        for (int j = 0; j < 32; j++) {
            float w = __expf(ar[j] - rmax) * rinv;     // masked -> exact 0
            ar[j] = w;
            Wt[(kh*32 + j)*P2Q + qr] = w;
        }
        __syncthreads();
        #pragma unroll 2
        for (int kk = 0; kk < 64; kk++) {
            float4 w0 = *(const float4*)(Wt + kk*P2Q + ty*8);
            float4 w1 = *(const float4*)(Wt + kk*P2Q + ty*8 + 4);
            float4 vv = *(const float4*)(Vs + kk*68 + tx*4);
            float wa[8] = {w0.x,w0.y,w0.z,w0.w, w1.x,w1.y,w1.z,w1.w};
            float va[4] = {vv.x,vv.y,vv.z,vv.w};
            #pragma unroll
            for (int i = 0; i < 8; i++)
                #pragma unroll
                for (int j = 0; j < 4; j++) Ov[i][j] += wa[i]*va[j];
        }
    }

    // zero-fill strictly-upper tail columns [q0+128, S)
    const int kstart = q0 + 128;
    if (kstart < SS) {
        const int len4 = (SS - kstart) >> 2;
        const int tot = 128 * len4;
        for (int idx = t; idx < tot; idx += 256) {
            int row = idx / len4, c = idx - row*len4;
            ((float4*)(attn + ((size_t)bh*SS + q0 + row)*SS + kstart))[c] =
                make_float4(0.f, 0.f, 0.f, 0.f);
        }
    }

    // O -> concat buffer [B,S,D]
    #pragma unroll
    for (int i = 0; i < 8; i++) {
        float* cr = g_c + ((size_t)b*SS + q0 + ty*8 + i)*DD + h*64 + tx*4;
        *(float4*)cr = make_float4(Ov[i][0], Ov[i][1], Ov[i][2], Ov[i][3]);
    }
}

// =================================================================================
// launch
// inputs: 0 v_in, 1 k_in, 2 q_in, 3 mask(unused), 4 Wq, 5 bq, 6 Wk, 7 bk,
//         8 Wv, 9 bv, 10 Wo, 11 bo, 12 E
// output: [output (B*S*D floats)] ++ [attention_weights (B*H*S*S floats)]
// =================================================================================
extern "C" void kernel_launch(void* const* d_in, const int* in_sizes, int n_in,
                              void* d_out, int out_size)
{
    (void)in_sizes; (void)n_in; (void)out_size;
    const float* v_in = (const float*)d_in[0];
    const float* k_in = (const float*)d_in[1];
    const float* q_in = (const float*)d_in[2];
    const float* Wq   = (const float*)d_in[4];
    const float* bq   = (const float*)d_in[5];
    const float* Wk   = (const float*)d_in[6];
    const float* bk   = (const float*)d_in[7];
    const float* Wv   = (const float*)d_in[8];
    const float* bv   = (const float*)d_in[9];
    const float* Wo   = (const float*)d_in[10];
    const float* bo   = (const float*)d_in[11];
    const float* E    = (const float*)d_in[12];

    float* out  = (float*)d_out;
    float* attn = out + (size_t)BSD;

    float *gq, *gk, *gv, *gc;
    cudaGetSymbolAddress((void**)&gq, g_q);
    cudaGetSymbolAddress((void**)&gk, g_k);
    cudaGetSymbolAddress((void**)&gv, g_v);
    cudaGetSymbolAddress((void**)&gc, g_c);

    cudaFuncSetAttribute(attn2,
                         cudaFuncAttributeMaxDynamicSharedMemorySize, SM2_BYTES);

    gemm_qkv<<<dim3(32, 4, 3), 256>>>(q_in, k_in, v_in,
                                      Wq, bq, Wk, bk, Wv, bv,
                                      gq, gk, gv);
    attn2<<<dim3(16, HH, BB), 256, SM2_BYTES>>>(E, attn);
    gemm_out<<<dim3(32, 4), 256>>>(gc, Wo, bo, out);
}

// round 12
// speedup vs baseline: 1.3555x; 1.3555x over previous
#include <cuda_runtime.h>
#include <cstddef>

// Problem constants
#define BB   2
#define SS   2048
#define DD   512
#define HH   8
#define DEP  64
#define BSD  (BB*SS*DD)

// attn smem pitches
#define PQ 68     // Qs [d][q]
#define PB 132    // Bs [d][0..128): K cols 0-63, E-new cols 64-127
#define PD 68     // DK [q][k]
#define PE 132    // DE ring [q][slot 0..127]
#define PV 68     // phase2 Vs/Wt pitch

// attn smem offsets (floats)
#define OFF_QS 0
#define OFF_BS 4352      // 64*68
#define OFF_DK 12800     // OFF_BS + 64*132
#define OFF_DE 17152     // OFF_DK + 64*68
#define OFF_RM 25600     // OFF_DE + 64*132
#define OFF_RS 25664
#define SMEM_FLOATS 25728
#define SMEM_BYTES  (SMEM_FLOATS*4)   // 102912

// ---------------- scratch (device globals; no allocation allowed) ----------------
__device__ float g_q[BB*HH*SS*DEP];   // [B,H,S,64] projected Q
__device__ float g_k[BB*HH*SS*DEP];   // [B,H,S,64] projected K
__device__ float g_v[BB*HH*SS*DEP];   // [B,H,S,64] projected V
__device__ float g_c[BB*SS*DD];       // [B,S,D] concat(attention)

// =================================================================================
// GEMM body: out[M=4096,N=512] = X[4096,512] @ W[512,512] + bias
// 128x128 tile, 256 threads, 8x8 per thread, K-chunks of 16, DOUBLE-BUFFERED
// (one __syncthreads per stage instead of two).
// mode 0: scatter to head-split layout [B,H,S,64]; mode 1: flat [M,N]
// =================================================================================
__device__ __forceinline__ void gemm_body(const float* __restrict__ X,
                                          const float* __restrict__ W,
                                          const float* __restrict__ bias,
                                          float* __restrict__ out, int mode)
{
    __shared__ float Xs[2][16*132];   // [buf][k][m], padded
    __shared__ float Wt[2][16*132];   // [buf][k][n], padded
    const int t  = threadIdx.x;
    const int tx = t & 15, ty = t >> 4;
    const int m0 = blockIdx.x * 128, n0 = blockIdx.y * 128;

    float acc[8][8];
    #pragma unroll
    for (int i = 0; i < 8; i++)
        #pragma unroll
        for (int j = 0; j < 8; j++) acc[i][j] = 0.f;

    // preload stage 0
    #pragma unroll
    for (int i = 0; i < 8; i++) {
        int idx = t + i*256;
        int k = idx & 15, m = idx >> 4;
        Xs[0][k*132 + m] = X[(size_t)(m0 + m)*DD + k];
    }
    #pragma unroll
    for (int i = 0; i < 8; i++) {
        int idx = t + i*256;
        int n = idx & 127, k = idx >> 7;
        Wt[0][k*132 + n] = W[(size_t)k*DD + n0 + n];
    }
    __syncthreads();

    const int NSTG = DD / 16;   // 32
    for (int s = 0; s < NSTG; s++) {
        const int cur = s & 1;
        // prefetch next stage into the other buffer
        if (s + 1 < NSTG) {
            const int nxt = cur ^ 1;
            const int kb = (s + 1) * 16;
            #pragma unroll
            for (int i = 0; i < 8; i++) {
                int idx = t + i*256;
                int k = idx & 15, m = idx >> 4;
                Xs[nxt][k*132 + m] = X[(size_t)(m0 + m)*DD + kb + k];
            }
            #pragma unroll
            for (int i = 0; i < 8; i++) {
                int idx = t + i*256;
                int n = idx & 127, k = idx >> 7;
                Wt[nxt][k*132 + n] = W[(size_t)(kb + k)*DD + n0 + n];
            }
        }
        // compute current stage
        #pragma unroll
        for (int k = 0; k < 16; k++) {
            float4 a0 = *(const float4*)&Xs[cur][k*132 + ty*8];
            float4 a1 = *(const float4*)&Xs[cur][k*132 + ty*8 + 4];
            float4 b0 = *(const float4*)&Wt[cur][k*132 + tx*8];
            float4 b1 = *(const float4*)&Wt[cur][k*132 + tx*8 + 4];
            float a[8] = {a0.x,a0.y,a0.z,a0.w,a1.x,a1.y,a1.z,a1.w};
            float b[8] = {b0.x,b0.y,b0.z,b0.w,b1.x,b1.y,b1.z,b1.w};
            #pragma unroll
            for (int i = 0; i < 8; i++)
                #pragma unroll
                for (int j = 0; j < 8; j++) acc[i][j] += a[i]*b[j];
        }
        __syncthreads();
    }

    #pragma unroll
    for (int i = 0; i < 8; i++) {
        int m = m0 + ty*8 + i;
        int b_ = m >> 11, s2 = m & (SS - 1);
        #pragma unroll
        for (int j = 0; j < 8; j++) {
            int n = n0 + tx*8 + j;
            float v = acc[i][j] + bias[n];
            if (mode == 0) {
                int h = n >> 6, d = n & 63;
                out[(((size_t)(b_*HH + h)*SS + s2) << 6) + d] = v;
            } else {
                out[(size_t)m*DD + n] = v;
            }
        }
    }
}

// Fused Q/K/V projections: blockIdx.z selects which projection. 384 CTAs.
__global__ __launch_bounds__(256, 2) void gemm_qkv(
    const float* __restrict__ q_in, const float* __restrict__ k_in,
    const float* __restrict__ v_in,
    const float* __restrict__ Wq, const float* __restrict__ bq,
    const float* __restrict__ Wk, const float* __restrict__ bk,
    const float* __restrict__ Wv, const float* __restrict__ bv,
    float* __restrict__ gq, float* __restrict__ gk, float* __restrict__ gv)
{
    const float *X, *W, *bias; float* out;
    if (blockIdx.z == 0)      { X = q_in; W = Wq; bias = bq; out = gq; }
    else if (blockIdx.z == 1) { X = k_in; W = Wk; bias = bk; out = gk; }
    else                      { X = v_in; W = Wv; bias = bv; out = gv; }
    gemm_body(X, W, bias, out, 0);
}

__global__ __launch_bounds__(256, 2) void gemm_out(
    const float* __restrict__ X, const float* __restrict__ W,
    const float* __restrict__ bias, float* __restrict__ out)
{
    gemm_body(X, W, bias, out, 1);
}

// =================================================================================
// Fused causal attention with relative position bias — rolling-E version.
// (VERBATIM the R6-measured kernel: 64-q tiles, 256 threads, 2 CTAs/SM.)
// =================================================================================
__global__ __launch_bounds__(256, 2) void attn_kernel(const float* __restrict__ E,
                                                      float* __restrict__ attn)
{
    extern __shared__ float sm[];
    float* Qs = sm + OFF_QS;
    float* Bs = sm + OFF_BS;
    float* DK = sm + OFF_DK;
    float* DE = sm + OFF_DE;
    float* rm = sm + OFF_RM;
    float* rs = sm + OFF_RS;

    const int t  = threadIdx.x;
    const int qt = 31 - (int)blockIdx.x;   // big tiles first
    const int q0 = qt * 64;
    const int h  = blockIdx.y, b = blockIdx.z;
    const int bh = b*HH + h;
    const float* qb = g_q + (size_t)bh*SS*DEP;
    const float* kb = g_k + (size_t)bh*SS*DEP;
    const float* vb = g_v + (size_t)bh*SS*DEP;
    float* arow_base = attn + ((size_t)bh*SS + q0) * SS;

    // load Q transposed: Qs[d][i] = Q[q0+i][d]
    for (int idx = t; idx < 64*DEP; idx += 256) {
        int i = idx >> 6, d = idx & 63;
        Qs[d*PQ + i] = qb[(size_t)(q0 + i)*DEP + d];
    }
    // prologue E rows: er0 + [0,64), er0 = S-64-q0 (always in range)
    {
        const int er0 = SS - 64 - q0;
        for (int idx = t; idx < 64*DEP; idx += 256) {
            int r = idx >> 6, d = idx & 63;
            Bs[d*PB + r] = E[(size_t)(er0 + r)*DEP + d];
        }
    }
    if (t < 64) { rm[t] = -1e30f; rs[t] = 0.f; }
    __syncthreads();

    const int ql = t >> 2, ks4 = t & 3;    // gather/stats mapping
    const int nch = qt + 1;

    // ---------------- prologue GEMM: DE slots [0,64) ----------------
    {
        const int rg = t >> 4, cg = t & 15;   // 4 rows x 4 cols per thread
        float acc[4][4];
        #pragma unroll
        for (int i = 0; i < 4; i++)
            #pragma unroll
            for (int j = 0; j < 4; j++) acc[i][j] = 0.f;
        const float* qcol = Qs + rg*4;
        const float* bcol = Bs + cg*4;
        #pragma unroll 4
        for (int d = 0; d < DEP; ++d) {
            float4 qv = *(const float4*)(qcol + d*PQ);
            float4 bv = *(const float4*)(bcol + d*PB);
            float qa[4] = {qv.x,qv.y,qv.z,qv.w};
            float ba[4] = {bv.x,bv.y,bv.z,bv.w};
            #pragma unroll
            for (int i = 0; i < 4; i++)
                #pragma unroll
                for (int j = 0; j < 4; j++) acc[i][j] += qa[i]*ba[j];
        }
        #pragma unroll
        for (int i = 0; i < 4; i++)
            *(float4*)(DE + (rg*4 + i)*PE + cg*4) =
                make_float4(acc[i][0], acc[i][1], acc[i][2], acc[i][3]);
    }
    __syncthreads();

    // ---------------- phase 1 main loop ----------------
    const int rg = t >> 4, cg = t & 15;   // GEMM: 4 rows x 8 cols per thread
    for (int kt = 0; kt < nch; ++kt) {
        const int k0 = kt*64;
        // load K transposed into cols [0,64)
        for (int idx = t; idx < 64*DEP; idx += 256) {
            int i = idx >> 6, d = idx & 63;
            Bs[d*PB + i] = kb[(size_t)(k0 + i)*DEP + d];
        }
        // load NEW E rows (er = S - q0 + 64*kt + r) into cols [64,128)
        {
            const int ern = SS - q0 + 64*kt;
            for (int idx = t; idx < 64*DEP; idx += 256) {
                int r = idx >> 6, d = idx & 63;
                int er = ern + r;
                Bs[d*PB + 64 + r] = (er < SS) ? E[(size_t)er*DEP + d] : 0.f;
            }
        }
        __syncthreads();

        // GEMM 64x128: acc 4x8 per thread
        float acc[4][8];
        #pragma unroll
        for (int i = 0; i < 4; i++)
            #pragma unroll
            for (int j = 0; j < 8; j++) acc[i][j] = 0.f;
        const float* qcol = Qs + rg*4;
        const float* bcol = Bs + cg*8;
        #pragma unroll 4
        for (int d = 0; d < DEP; ++d) {
            float4 qv = *(const float4*)(qcol + d*PQ);
            float4 b0 = *(const float4*)(bcol + d*PB);
            float4 b1 = *(const float4*)(bcol + d*PB + 4);
            float qa[4] = {qv.x,qv.y,qv.z,qv.w};
            float bb[8] = {b0.x,b0.y,b0.z,b0.w, b1.x,b1.y,b1.z,b1.w};
            #pragma unroll
            for (int i = 0; i < 4; i++)
                #pragma unroll
                for (int j = 0; j < 8; j++) acc[i][j] += qa[i]*bb[j];
        }

        // writeback: cg<8 -> DK, cg>=8 -> DE new slots
        if (cg < 8) {
            #pragma unroll
            for (int i = 0; i < 4; i++) {
                float* dr = DK + (rg*4 + i)*PD + cg*8;
                ((float4*)dr)[0] = make_float4(acc[i][0], acc[i][1], acc[i][2], acc[i][3]);
                ((float4*)dr)[1] = make_float4(acc[i][4], acc[i][5], acc[i][6], acc[i][7]);
            }
        } else {
            const int sb = (64*(kt + 1)) & 127;      // new-slot base (0 or 64)
            const int c0 = sb + (cg - 8)*8;
            #pragma unroll
            for (int i = 0; i < 4; i++) {
                float* dr = DE + (rg*4 + i)*PE + c0;
                ((float4*)dr)[0] = make_float4(acc[i][0], acc[i][1], acc[i][2], acc[i][3]);
                ((float4*)dr)[1] = make_float4(acc[i][4], acc[i][5], acc[i][6], acc[i][7]);
            }
        }
        __syncthreads();

        // skew-gather + mask + stats + raw-logit store
        const float* dkr = DK + ql*PD;
        const float* der = DE + ql*PE;
        const int slotbase = 64*kt + 63 - ql;   // >= 0
        float l[16];
        float lmax = -1e30f;
        #pragma unroll
        for (int j = 0; j < 16; j++) {
            int kl = ks4 + 4*j;
            float v = dkr[kl] + der[(slotbase + kl) & 127];
            v = (k0 + kl <= q0 + ql) ? v*0.125f : -1e30f;
            l[j] = v;
            lmax = fmaxf(lmax, v);
        }
        float lsum = 0.f;
        #pragma unroll
        for (int j = 0; j < 16; j++) lsum += __expf(l[j] - lmax);

        float* ar = arow_base + (size_t)ql*SS + k0;
        #pragma unroll
        for (int j = 0; j < 16; j++) ar[ks4 + 4*j] = l[j];

        #pragma unroll
        for (int off = 1; off < 4; off <<= 1) {
            float om = __shfl_xor_sync(0xffffffffu, lmax, off);
            float os = __shfl_xor_sync(0xffffffffu, lsum, off);
            float nm = fmaxf(lmax, om);
            lsum = lsum*__expf(lmax - nm) + os*__expf(om - nm);
            lmax = nm;
        }
        if (ks4 == 0) {
            float mo = rm[ql];
            float nm = fmaxf(mo, lmax);
            rs[ql] = rs[ql]*__expf(mo - nm) + lsum*__expf(lmax - nm);
            rm[ql] = nm;
        }
        __syncthreads();   // rm/rs visible; DK/DE reads done before next writeback
    }

    const float rmax = rm[ql];
    const float rinv = 1.f / rs[ql];

    // ---------------- phase 2: normalize + O = W @ V ----------------
    const int tx = t & 15, ty = t >> 4;    // 4x4 tile per thread
    float* Vs = sm + OFF_BS;               // [k][d] pitch PV
    float* Wt = sm + OFF_BS + 4352;        // [k][q] pitch PV
    float Ov[4][4];
    #pragma unroll
    for (int i = 0; i < 4; i++)
        #pragma unroll
        for (int j = 0; j < 4; j++) Ov[i][j] = 0.f;

    for (int kt = 0; kt < nch; ++kt) {
        const int k0 = kt*64;
        __syncthreads();   // previous-iteration Vs/Wt reads complete
        for (int idx = t; idx < 64*DEP; idx += 256) {
            int i = idx >> 6, d = idx & 63;
            Vs[i*PV + d] = vb[(size_t)(k0 + i)*DEP + d];
        }
        float* ar = arow_base + (size_t)ql*SS + k0;
        #pragma unroll
        for (int j = 0; j < 16; j++) {
            int kl = ks4 + 4*j;
            float w = __expf(ar[kl] - rmax) * rinv;   // masked -> exact 0
            ar[kl] = w;
            Wt[kl*PV + ql] = w;
        }
        __syncthreads();
        #pragma unroll 4
        for (int kk = 0; kk < 64; ++kk) {
            float4 wv = *(const float4*)(Wt + kk*PV + ty*4);
            float4 vv = *(const float4*)(Vs + kk*PV + tx*4);
            float wa[4] = {wv.x, wv.y, wv.z, wv.w};
            float va[4] = {vv.x, vv.y, vv.z, vv.w};
            #pragma unroll
            for (int i = 0; i < 4; i++)
                #pragma unroll
                for (int j = 0; j < 4; j++) Ov[i][j] += wa[i]*va[j];
        }
    }

    // zero-fill strictly-upper tail columns [nch*64, S)
    const int kstart = nch*64;
    if (kstart < SS) {
        const int len4 = (SS - kstart) >> 2;
        const int tot = 64 * len4;
        for (int idx = t; idx < tot; idx += 256) {
            int row = idx / len4, c = idx - row*len4;
            ((float4*)(arow_base + (size_t)row*SS + kstart))[c] =
                make_float4(0.f, 0.f, 0.f, 0.f);
        }
    }

    // O -> concat buffer [B,S,D]
    #pragma unroll
    for (int i = 0; i < 4; i++) {
        float* cr = g_c + ((size_t)b*SS + q0 + ty*4 + i)*DD + h*64 + tx*4;
        *(float4*)cr = make_float4(Ov[i][0], Ov[i][1], Ov[i][2], Ov[i][3]);
    }
}

// =================================================================================
// launch
// inputs: 0 v_in, 1 k_in, 2 q_in, 3 mask(unused), 4 Wq, 5 bq, 6 Wk, 7 bk,
//         8 Wv, 9 bv, 10 Wo, 11 bo, 12 E
// output: [output (B*S*D floats)] ++ [attention_weights (B*H*S*S floats)]
// =================================================================================
extern "C" void kernel_launch(void* const* d_in, const int* in_sizes, int n_in,
                              void* d_out, int out_size)
{
    (void)in_sizes; (void)n_in; (void)out_size;
    const float* v_in = (const float*)d_in[0];
    const float* k_in = (const float*)d_in[1];
    const float* q_in = (const float*)d_in[2];
    const float* Wq   = (const float*)d_in[4];
    const float* bq   = (const float*)d_in[5];
    const float* Wk   = (const float*)d_in[6];
    const float* bk   = (const float*)d_in[7];
    const float* Wv   = (const float*)d_in[8];
    const float* bv   = (const float*)d_in[9];
    const float* Wo   = (const float*)d_in[10];
    const float* bo   = (const float*)d_in[11];
    const float* E    = (const float*)d_in[12];

    float* out  = (float*)d_out;
    float* attn = out + (size_t)BSD;

    float *gq, *gk, *gv, *gc;
    cudaGetSymbolAddress((void**)&gq, g_q);
    cudaGetSymbolAddress((void**)&gk, g_k);
    cudaGetSymbolAddress((void**)&gv, g_v);
    cudaGetSymbolAddress((void**)&gc, g_c);

    cudaFuncSetAttribute(attn_kernel,
                         cudaFuncAttributeMaxDynamicSharedMemorySize, SMEM_BYTES);

    gemm_qkv<<<dim3(32, 4, 3), 256>>>(q_in, k_in, v_in,
                                      Wq, bq, Wk, bk, Wv, bv,
                                      gq, gk, gv);
    attn_kernel<<<dim3(32, HH, BB), 256, SMEM_BYTES>>>(E, attn);
    gemm_out<<<dim3(32, 4), 256>>>(gc, Wo, bo, out);
}

// round 13
// speedup vs baseline: 2.1353x; 1.5752x over previous
#include <cuda_runtime.h>
#include <cuda_bf16.h>
#include <cstdint>
#include <cstddef>

// Problem constants
#define BB   2
#define SS   2048
#define DD   512
#define HH   8
#define DEP  64
#define BSD  (BB*SS*DD)

// ---------------- scratch (device globals; no allocation allowed) ----------------
__device__ float g_q[BB*HH*SS*DEP];   // [B,H,S,64] projected Q
__device__ float g_k[BB*HH*SS*DEP];   // [B,H,S,64] projected K
__device__ float g_v[BB*HH*SS*DEP];   // [B,H,S,64] projected V
__device__ float g_c[BB*SS*DD];       // [B,S,D] concat(attention)

// =================================================================================
// Projection GEMMs (R12 measured version, unchanged)
// =================================================================================
__device__ __forceinline__ void gemm_body(const float* __restrict__ X,
                                          const float* __restrict__ W,
                                          const float* __restrict__ bias,
                                          float* __restrict__ out, int mode)
{
    __shared__ float Xs[2][16*132];
    __shared__ float Wt[2][16*132];
    const int t  = threadIdx.x;
    const int tx = t & 15, ty = t >> 4;
    const int m0 = blockIdx.x * 128, n0 = blockIdx.y * 128;

    float acc[8][8];
    #pragma unroll
    for (int i = 0; i < 8; i++)
        #pragma unroll
        for (int j = 0; j < 8; j++) acc[i][j] = 0.f;

    #pragma unroll
    for (int i = 0; i < 8; i++) {
        int idx = t + i*256;
        int k = idx & 15, m = idx >> 4;
        Xs[0][k*132 + m] = X[(size_t)(m0 + m)*DD + k];
    }
    #pragma unroll
    for (int i = 0; i < 8; i++) {
        int idx = t + i*256;
        int n = idx & 127, k = idx >> 7;
        Wt[0][k*132 + n] = W[(size_t)k*DD + n0 + n];
    }
    __syncthreads();

    const int NSTG = DD / 16;
    for (int s = 0; s < NSTG; s++) {
        const int cur = s & 1;
        if (s + 1 < NSTG) {
            const int nxt = cur ^ 1;
            const int kb = (s + 1) * 16;
            #pragma unroll
            for (int i = 0; i < 8; i++) {
                int idx = t + i*256;
                int k = idx & 15, m = idx >> 4;
                Xs[nxt][k*132 + m] = X[(size_t)(m0 + m)*DD + kb + k];
            }
            #pragma unroll
            for (int i = 0; i < 8; i++) {
                int idx = t + i*256;
                int n = idx & 127, k = idx >> 7;
                Wt[nxt][k*132 + n] = W[(size_t)(kb + k)*DD + n0 + n];
            }
        }
        #pragma unroll
        for (int k = 0; k < 16; k++) {
            float4 a0 = *(const float4*)&Xs[cur][k*132 + ty*8];
            float4 a1 = *(const float4*)&Xs[cur][k*132 + ty*8 + 4];
            float4 b0 = *(const float4*)&Wt[cur][k*132 + tx*8];
            float4 b1 = *(const float4*)&Wt[cur][k*132 + tx*8 + 4];
            float a[8] = {a0.x,a0.y,a0.z,a0.w,a1.x,a1.y,a1.z,a1.w};
            float b[8] = {b0.x,b0.y,b0.z,b0.w,b1.x,b1.y,b1.z,b1.w};
            #pragma unroll
            for (int i = 0; i < 8; i++)
                #pragma unroll
                for (int j = 0; j < 8; j++) acc[i][j] += a[i]*b[j];
        }
        __syncthreads();
    }

    #pragma unroll
    for (int i = 0; i < 8; i++) {
        int m = m0 + ty*8 + i;
        int b_ = m >> 11, s2 = m & (SS - 1);
        #pragma unroll
        for (int j = 0; j < 8; j++) {
            int n = n0 + tx*8 + j;
            float v = acc[i][j] + bias[n];
            if (mode == 0) {
                int h = n >> 6, d = n & 63;
                out[(((size_t)(b_*HH + h)*SS + s2) << 6) + d] = v;
            } else {
                out[(size_t)m*DD + n] = v;
            }
        }
    }
}

__global__ __launch_bounds__(256, 2) void gemm_qkv(
    const float* __restrict__ q_in, const float* __restrict__ k_in,
    const float* __restrict__ v_in,
    const float* __restrict__ Wq, const float* __restrict__ bq,
    const float* __restrict__ Wk, const float* __restrict__ bk,
    const float* __restrict__ Wv, const float* __restrict__ bv,
    float* __restrict__ gq, float* __restrict__ gk, float* __restrict__ gv)
{
    const float *X, *W, *bias; float* out;
    if (blockIdx.z == 0)      { X = q_in; W = Wq; bias = bq; out = gq; }
    else if (blockIdx.z == 1) { X = k_in; W = Wk; bias = bk; out = gk; }
    else                      { X = v_in; W = Wv; bias = bv; out = gv; }
    gemm_body(X, W, bias, out, 0);
}

__global__ __launch_bounds__(256, 2) void gemm_out(
    const float* __restrict__ X, const float* __restrict__ W,
    const float* __restrict__ bias, float* __restrict__ out)
{
    gemm_body(X, W, bias, out, 1);
}

// =================================================================================
// bf16 split helpers + mma.sync machinery
// =================================================================================
__device__ __forceinline__ uint32_t sptr(const void* p) {
    return (uint32_t)__cvta_generic_to_shared(p);
}
__device__ __forceinline__ void split4(float4 v, uint2& hi, uint2& lo) {
    __nv_bfloat16 h0=__float2bfloat16(v.x), h1=__float2bfloat16(v.y),
                  h2=__float2bfloat16(v.z), h3=__float2bfloat16(v.w);
    __nv_bfloat16 l0=__float2bfloat16(v.x-__bfloat162float(h0)),
                  l1=__float2bfloat16(v.y-__bfloat162float(h1)),
                  l2=__float2bfloat16(v.z-__bfloat162float(h2)),
                  l3=__float2bfloat16(v.w-__bfloat162float(h3));
    __nv_bfloat162 ph0=__halves2bfloat162(h0,h1), ph1=__halves2bfloat162(h2,h3);
    __nv_bfloat162 pl0=__halves2bfloat162(l0,l1), pl1=__halves2bfloat162(l2,l3);
    hi = make_uint2(*(uint32_t*)&ph0, *(uint32_t*)&ph1);
    lo = make_uint2(*(uint32_t*)&pl0, *(uint32_t*)&pl1);
}
__device__ __forceinline__ void bsplit(float x, __nv_bfloat16& h, __nv_bfloat16& l) {
    h = __float2bfloat16(x);
    l = __float2bfloat16(x - __bfloat162float(h));
}

// pitch 72 bf16 = 144 bytes per row (conflict-free for ldmatrix: 16B bank shift/row)
#define PH 72
// A fragment (m16k16): rows Rb + (lane&15), k-half (lane>>4)
#define LDSM_X4(r, base_chr, Rb, kelem) do {                                        \
    uint32_t _a = sptr((base_chr) + ((Rb) + (lane & 15))*144 + (kelem)*2            \
                       + ((lane >> 4) & 1)*16);                                     \
    asm volatile("ldmatrix.sync.aligned.m8n8.x4.shared.b16 {%0,%1,%2,%3}, [%4];"    \
        : "=r"((r)[0]),"=r"((r)[1]),"=r"((r)[2]),"=r"((r)[3]) : "r"(_a)); } while(0)
// B fragment (n8k16) from [n][k] storage: rows Nb + (lane&7), k-half (lane>>3)&1
#define LDSM_X2(r, base_chr, Nb, kelem) do {                                        \
    uint32_t _a = sptr((base_chr) + ((Nb) + (lane & 7))*144 + (kelem)*2             \
                       + ((lane >> 3) & 1)*16);                                     \
    asm volatile("ldmatrix.sync.aligned.m8n8.x2.shared.b16 {%0,%1}, [%2];"          \
        : "=r"((r)[0]),"=r"((r)[1]) : "r"(_a)); } while(0)
#define MMA_BF16(c, a, bb)                                                          \
    asm volatile("mma.sync.aligned.m16n8k16.row.col.f32.bf16.bf16.f32 "             \
        "{%0,%1,%2,%3}, {%4,%5,%6,%7}, {%8,%9}, {%0,%1,%2,%3};"                     \
        : "+f"((c)[0]),"+f"((c)[1]),"+f"((c)[2]),"+f"((c)[3])                       \
        : "r"((a)[0]),"r"((a)[1]),"r"((a)[2]),"r"((a)[3]), "r"((bb)[0]),"r"((bb)[1]))

// smem byte offsets
#define B_QH 0
#define B_QL 9216
#define B_BH 18432
#define B_BL 36864
#define B_DK 55296      // float [64][68]
#define B_DE 72704      // float [64][132] ring (128 slots)
#define B_RM 106496
#define B_RS 106752
#define SM3_BYTES 107008
// phase-2 overlays (inside B region)
#define B_VH 18432
#define B_VL 27648
#define B_P2H 36864
#define B_P2L 46080

// =================================================================================
// Tensor-core fused attention. Same structure as the measured R6 kernel
// (64-q tiles, rolling-E ring, 2 CTAs/SM); GEMMs via mma.sync bf16 split-3.
// =================================================================================
__global__ __launch_bounds__(256, 2) void attn3(const float* __restrict__ E,
                                                float* __restrict__ attn)
{
    extern __shared__ char smc[];
    float* DK = (float*)(smc + B_DK);
    float* DE = (float*)(smc + B_DE);
    float* rm = (float*)(smc + B_RM);
    float* rs = (float*)(smc + B_RS);

    const int t    = threadIdx.x;
    const int lane = t & 31, wp = t >> 5;
    const int mi = wp & 3, nh = wp >> 2;
    const int qt = 31 - (int)blockIdx.x;   // big tiles first
    const int q0 = qt * 64;
    const int h  = blockIdx.y, b = blockIdx.z;
    const int bh = b*HH + h;
    const float* qb = g_q + (size_t)bh*SS*DEP;
    const float* kb = g_k + (size_t)bh*SS*DEP;
    const float* vb = g_v + (size_t)bh*SS*DEP;
    float* arow_base = attn + ((size_t)bh*SS + q0) * SS;
    const int ql = t >> 2, ks4 = t & 3;
    const int nch = qt + 1;

    // ---- load Q (split) + prologue E rows into B[0,64) (split) ----
    #pragma unroll
    for (int it = 0; it < 4; it++) {
        int idx = t + it*256;               // 1024 float4s
        int r = idx >> 4, d4 = (idx & 15) << 2;
        float4 v = *(const float4*)(qb + (size_t)(q0 + r)*DEP + d4);
        uint2 hi, lo; split4(v, hi, lo);
        *(uint2*)(smc + B_QH + r*144 + d4*2) = hi;
        *(uint2*)(smc + B_QL + r*144 + d4*2) = lo;
    }
    {
        const int er0 = SS - 64 - q0;       // always in range
        #pragma unroll
        for (int it = 0; it < 4; it++) {
            int idx = t + it*256;
            int r = idx >> 4, d4 = (idx & 15) << 2;
            float4 v = *(const float4*)(E + (size_t)(er0 + r)*DEP + d4);
            uint2 hi, lo; split4(v, hi, lo);
            *(uint2*)(smc + B_BH + r*144 + d4*2) = hi;
            *(uint2*)(smc + B_BL + r*144 + d4*2) = lo;
        }
    }
    if (t < 64) { rm[t] = -1e30f; rs[t] = 0.f; }
    __syncthreads();

    // ---- prologue MMA: Q @ E_pro^T -> DE slots [0,64). warp: mi rows, 4 n-tiles ----
    {
        float c[4][4];
        #pragma unroll
        for (int j = 0; j < 4; j++)
            #pragma unroll
            for (int e = 0; e < 4; e++) c[j][e] = 0.f;
        uint32_t Ah[4], Al[4], Bh[2], Bl[2];
        #pragma unroll
        for (int ks = 0; ks < 4; ks++) {
            LDSM_X4(Ah, smc + B_QH, mi*16, ks*16);
            LDSM_X4(Al, smc + B_QL, mi*16, ks*16);
            #pragma unroll
            for (int j = 0; j < 4; j++) {
                int n0 = (nh*4 + j)*8;
                LDSM_X2(Bh, smc + B_BH, n0, ks*16);
                LDSM_X2(Bl, smc + B_BL, n0, ks*16);
                MMA_BF16(c[j], Ah, Bh);
                MMA_BF16(c[j], Ah, Bl);
                MMA_BF16(c[j], Al, Bh);
            }
        }
        int r = mi*16 + (lane >> 2), cc = 2*(lane & 3);
        #pragma unroll
        for (int j = 0; j < 4; j++) {
            int col = (nh*4 + j)*8 + cc;    // slot 0..63
            *(float2*)(DE + r*132 + col)       = make_float2(c[j][0], c[j][1]);
            *(float2*)(DE + (r + 8)*132 + col) = make_float2(c[j][2], c[j][3]);
        }
    }
    __syncthreads();

    // ---------------- phase 1 main loop ----------------
    for (int kt = 0; kt < nch; kt++) {
        const int k0 = kt*64;
        // K -> B rows [0,64)
        #pragma unroll
        for (int it = 0; it < 4; it++) {
            int idx = t + it*256;
            int r = idx >> 4, d4 = (idx & 15) << 2;
            float4 v = *(const float4*)(kb + (size_t)(k0 + r)*DEP + d4);
            uint2 hi, lo; split4(v, hi, lo);
            *(uint2*)(smc + B_BH + r*144 + d4*2) = hi;
            *(uint2*)(smc + B_BL + r*144 + d4*2) = lo;
        }
        // new E rows -> B rows [64,128)
        {
            const int ern = SS - q0 + 64*kt;
            #pragma unroll
            for (int it = 0; it < 4; it++) {
                int idx = t + it*256;
                int r = idx >> 4, d4 = (idx & 15) << 2;
                int er = ern + r;
                float4 v = (er < SS) ? *(const float4*)(E + (size_t)er*DEP + d4)
                                     : make_float4(0.f, 0.f, 0.f, 0.f);
                uint2 hi, lo; split4(v, hi, lo);
                *(uint2*)(smc + B_BH + (64 + r)*144 + d4*2) = hi;
                *(uint2*)(smc + B_BL + (64 + r)*144 + d4*2) = lo;
            }
        }
        __syncthreads();

        // D(64x128) = Q @ B^T; warp: mi rows, n-tiles nh*8..+8
        float c[8][4];
        #pragma unroll
        for (int j = 0; j < 8; j++)
            #pragma unroll
            for (int e = 0; e < 4; e++) c[j][e] = 0.f;
        {
            uint32_t Ah[4], Al[4], Bh[2], Bl[2];
            #pragma unroll
            for (int ks = 0; ks < 4; ks++) {
                LDSM_X4(Ah, smc + B_QH, mi*16, ks*16);
                LDSM_X4(Al, smc + B_QL, mi*16, ks*16);
                #pragma unroll
                for (int j = 0; j < 8; j++) {
                    int n0 = (nh*8 + j)*8;
                    LDSM_X2(Bh, smc + B_BH, n0, ks*16);
                    LDSM_X2(Bl, smc + B_BL, n0, ks*16);
                    MMA_BF16(c[j], Ah, Bh);
                    MMA_BF16(c[j], Ah, Bl);
                    MMA_BF16(c[j], Al, Bh);
                }
            }
        }
        {
            int r = mi*16 + (lane >> 2), cc = 2*(lane & 3);
            if (nh == 0) {                       // K-dots -> DK[q][k]
                #pragma unroll
                for (int j = 0; j < 8; j++) {
                    int col = j*8 + cc;
                    *(float2*)(DK + r*68 + col)       = make_float2(c[j][0], c[j][1]);
                    *(float2*)(DK + (r + 8)*68 + col) = make_float2(c[j][2], c[j][3]);
                }
            } else {                             // E-dots -> ring new slots
                int sb = (64*(kt + 1)) & 127;    // 0 or 64
                #pragma unroll
                for (int j = 0; j < 8; j++) {
                    int slot = sb + j*8 + cc;
                    *(float2*)(DE + r*132 + slot)       = make_float2(c[j][0], c[j][1]);
                    *(float2*)(DE + (r + 8)*132 + slot) = make_float2(c[j][2], c[j][3]);
                }
            }
        }
        __syncthreads();

        // skew-gather + mask + stats + raw-logit store (identical to R6)
        const float* dkr = DK + ql*68;
        const float* der = DE + ql*132;
        const int slotbase = 64*kt + 63 - ql;
        float l[16];
        float lmax = -1e30f;
        #pragma unroll
        for (int j = 0; j < 16; j++) {
            int kl = ks4 + 4*j;
            float v = dkr[kl] + der[(slotbase + kl) & 127];
            v = (k0 + kl <= q0 + ql) ? v*0.125f : -1e30f;
            l[j] = v;
            lmax = fmaxf(lmax, v);
        }
        float lsum = 0.f;
        #pragma unroll
        for (int j = 0; j < 16; j++) lsum += __expf(l[j] - lmax);

        float* ar = arow_base + (size_t)ql*SS + k0;
        #pragma unroll
        for (int j = 0; j < 16; j++) ar[ks4 + 4*j] = l[j];

        #pragma unroll
        for (int off = 1; off < 4; off <<= 1) {
            float om = __shfl_xor_sync(0xffffffffu, lmax, off);
            float os = __shfl_xor_sync(0xffffffffu, lsum, off);
            float nm = fmaxf(lmax, om);
            lsum = lsum*__expf(lmax - nm) + os*__expf(om - nm);
            lmax = nm;
        }
        if (ks4 == 0) {
            float mo = rm[ql];
            float nm = fmaxf(mo, lmax);
            rs[ql] = rs[ql]*__expf(mo - nm) + lsum*__expf(lmax - nm);
            rm[ql] = nm;
        }
        __syncthreads();
    }

    const float rmax = rm[ql];
    const float rinv = 1.f / rs[ql];

    // ---------------- phase 2: normalize + O = P @ V (mma) ----------------
    __nv_bfloat16* Vh  = (__nv_bfloat16*)(smc + B_VH);
    __nv_bfloat16* Vl  = (__nv_bfloat16*)(smc + B_VL);
    __nv_bfloat16* P2h = (__nv_bfloat16*)(smc + B_P2H);
    __nv_bfloat16* P2l = (__nv_bfloat16*)(smc + B_P2L);
    float o[4][4];
    #pragma unroll
    for (int j = 0; j < 4; j++)
        #pragma unroll
        for (int e = 0; e < 4; e++) o[j][e] = 0.f;

    for (int kt = 0; kt < nch; kt++) {
        const int k0 = kt*64;
        __syncthreads();   // previous-iteration MMA reads complete
        // V transposed: Vh[d][k] = V[k0+k][d]
        #pragma unroll
        for (int it = 0; it < 4; it++) {
            int idx = t + it*256;
            int k = idx >> 4, d4 = (idx & 15) << 2;
            float4 v = *(const float4*)(vb + (size_t)(k0 + k)*DEP + d4);
            float vv[4] = {v.x, v.y, v.z, v.w};
            #pragma unroll
            for (int e = 0; e < 4; e++) {
                __nv_bfloat16 hb, lb; bsplit(vv[e], hb, lb);
                Vh[(d4 + e)*PH + k] = hb;
                Vl[(d4 + e)*PH + k] = lb;
            }
        }
        // normalize weights (gmem) + P split
        float* ar = arow_base + (size_t)ql*SS + k0;
        #pragma unroll
        for (int j = 0; j < 16; j++) {
            int kl = ks4 + 4*j;
            float wgt = __expf(ar[kl] - rmax) * rinv;   // masked -> exact 0
            ar[kl] = wgt;
            __nv_bfloat16 hb, lb; bsplit(wgt, hb, lb);
            P2h[ql*PH + kl] = hb;
            P2l[ql*PH + kl] = lb;
        }
        __syncthreads();
        // O += P @ V^T(storage): warp mi rows, 4 d-tiles (nh*4+j)
        {
            uint32_t Ah[4], Al[4], Bh[2], Bl[2];
            #pragma unroll
            for (int ks = 0; ks < 4; ks++) {
                LDSM_X4(Ah, smc + B_P2H, mi*16, ks*16);
                LDSM_X4(Al, smc + B_P2L, mi*16, ks*16);
                #pragma unroll
                for (int j = 0; j < 4; j++) {
                    int n0 = (nh*4 + j)*8;
                    LDSM_X2(Bh, smc + B_VH, n0, ks*16);
                    LDSM_X2(Bl, smc + B_VL, n0, ks*16);
                    MMA_BF16(o[j], Ah, Bh);
                    MMA_BF16(o[j], Ah, Bl);
                    MMA_BF16(o[j], Al, Bh);
                }
            }
        }
    }

    // zero-fill strictly-upper tail columns [nch*64, S)
    const int kstart = nch*64;
    if (kstart < SS) {
        const int len4 = (SS - kstart) >> 2;
        const int tot = 64 * len4;
        for (int idx = t; idx < tot; idx += 256) {
            int row = idx / len4, ccc = idx - row*len4;
            ((float4*)(arow_base + (size_t)row*SS + kstart))[ccc] =
                make_float4(0.f, 0.f, 0.f, 0.f);
        }
    }

    // O -> concat buffer [B,S,D]
    {
        int r = mi*16 + (lane >> 2), cc = 2*(lane & 3);
        #pragma unroll
        for (int j = 0; j < 4; j++) {
            int d = (nh*4 + j)*8 + cc;
            *(float2*)(g_c + ((size_t)b*SS + q0 + r)*DD + h*64 + d) =
                make_float2(o[j][0], o[j][1]);
            *(float2*)(g_c + ((size_t)b*SS + q0 + r + 8)*DD + h*64 + d) =
                make_float2(o[j][2], o[j][3]);
        }
    }
}

// =================================================================================
// launch
// inputs: 0 v_in, 1 k_in, 2 q_in, 3 mask(unused), 4 Wq, 5 bq, 6 Wk, 7 bk,
//         8 Wv, 9 bv, 10 Wo, 11 bo, 12 E
// output: [output (B*S*D floats)] ++ [attention_weights (B*H*S*S floats)]
// =================================================================================
extern "C" void kernel_launch(void* const* d_in, const int* in_sizes, int n_in,
                              void* d_out, int out_size)
{
    (void)in_sizes; (void)n_in; (void)out_size;
    const float* v_in = (const float*)d_in[0];
    const float* k_in = (const float*)d_in[1];
    const float* q_in = (const float*)d_in[2];
    const float* Wq   = (const float*)d_in[4];
    const float* bq   = (const float*)d_in[5];
    const float* Wk   = (const float*)d_in[6];
    const float* bk   = (const float*)d_in[7];
    const float* Wv   = (const float*)d_in[8];
    const float* bv   = (const float*)d_in[9];
    const float* Wo   = (const float*)d_in[10];
    const float* bo   = (const float*)d_in[11];
    const float* E    = (const float*)d_in[12];

    float* out  = (float*)d_out;
    float* attn = out + (size_t)BSD;

    float *gq, *gk, *gv, *gc;
    cudaGetSymbolAddress((void**)&gq, g_q);
    cudaGetSymbolAddress((void**)&gk, g_k);
    cudaGetSymbolAddress((void**)&gv, g_v);
    cudaGetSymbolAddress((void**)&gc, g_c);

    cudaFuncSetAttribute(attn3,
                         cudaFuncAttributeMaxDynamicSharedMemorySize, SM3_BYTES);

    gemm_qkv<<<dim3(32, 4, 3), 256>>>(q_in, k_in, v_in,
                                      Wq, bq, Wk, bk, Wv, bv,
                                      gq, gk, gv);
    attn3<<<dim3(32, HH, BB), 256, SM3_BYTES>>>(E, attn);
    gemm_out<<<dim3(32, 4), 256>>>(gc, Wo, bo, out);
}